// round 14
// baseline (speedup 1.0000x reference)
#include <cuda_runtime.h>
#include <cuda_fp16.h>
#include <cstdint>

// ---------------- problem constants ------------------------------------------
#define BATCH 8192
#define I_DIM 512
#define H_DIM 1024
#define D_DIM 8
#define G3H   3072

// ---------------- GEMM tiling (NO K padding; biases applied in epilogue) -----
#define BM 128               // batch rows per tile
#define BN 64                // hidden cols per tile (per gate; 3 gates)
#define KC 64                // halves per K-chunk
#define NCHUNK1 8            // 512/64   (x @ W_ih^T)
#define NCHUNKS 24           // + 1024/64 (h' @ W_hh^T)
#define NTILES 1024          // (8192/128) * (1024/64)
#define NSTAGE 4
#define SPITCH 144           // bytes per SMEM row (64 halves + 8 pad)
#define SROWS (BM + 3 * BN)  // 128 A rows + 192 B rows = 320
#define STAGE_BYTES (SROWS * SPITCH)            // 46080
#define BAR_BYTES 64
#define SMEM_ALLOC (NSTAGE * STAGE_BYTES + BAR_BYTES + 256)
#define NTHREADS 576         // 16 consumer warps + 2 producer warps
#define NCONS 512
#define NPROD 64

// ---------------- device scratch ---------------------------------------------
__device__ __half g_x16[BATCH * I_DIM];
__device__ __half g_h16[BATCH * H_DIM];
__device__ __half g_wih[G3H * I_DIM];
__device__ __half g_whh[G3H * H_DIM];

// ---------------- PTX helpers ------------------------------------------------
__device__ __forceinline__ uint32_t smem_u32(const void* p) {
    uint32_t a;
    asm("{ .reg .u64 t; cvta.to.shared.u64 t, %1; cvt.u32.u64 %0, t; }"
        : "=r"(a) : "l"(p));
    return a;
}
__device__ __forceinline__ void cp16(uint32_t dst, const void* src) {
    asm volatile("cp.async.cg.shared.global [%0], [%1], 16;" :: "r"(dst), "l"(src));
}
#define MBAR_INIT(a, c)  asm volatile("mbarrier.init.shared.b64 [%0], %1;" :: "r"(a), "r"(c) : "memory")
#define MBAR_ARRIVE(a)   asm volatile("mbarrier.arrive.shared.b64 _, [%0];" :: "r"(a) : "memory")
#define CP_MBAR_ARRIVE(a) asm volatile("cp.async.mbarrier.arrive.noinc.shared.b64 [%0];" :: "r"(a) : "memory")
__device__ __forceinline__ void mbar_wait(uint32_t mbar, uint32_t parity) {
    asm volatile(
        "{\n\t.reg .pred P;\n"
        "LAB_%=:\n\t"
        "mbarrier.try_wait.parity.acquire.cta.shared::cta.b64 P, [%0], %1, 0x989680;\n\t"
        "@!P bra LAB_%=;\n\t}"
        :: "r"(mbar), "r"(parity) : "memory");
}
#define LDSM4(r0, r1, r2, r3, addr) \
    asm volatile("ldmatrix.sync.aligned.m8n8.x4.shared.b16 {%0,%1,%2,%3}, [%4];" \
        : "=r"(r0), "=r"(r1), "=r"(r2), "=r"(r3) : "r"(addr))
#define MMA16816(acc, a0, a1, a2, a3, b0, b1) \
    asm volatile( \
        "mma.sync.aligned.m16n8k16.row.col.f32.f16.f16.f32 " \
        "{%0,%1,%2,%3}, {%4,%5,%6,%7}, {%8,%9}, {%0,%1,%2,%3};" \
        : "+f"((acc)[0]), "+f"((acc)[1]), "+f"((acc)[2]), "+f"((acc)[3]) \
        : "r"(a0), "r"(a1), "r"(a2), "r"(a3), "r"(b0), "r"(b1))

// ---------------- fused prep kernel ------------------------------------------
// block ranges: [0,2048) gamma_h (4 rows each) | [2048,3072) x | [3072,3584) wih
//               | [3584,4608) whh  — converts are PURE flat streams (no index math)
#define GH_BLOCKS 2048
#define GH_ROWS 4
#define CVX_BLOCKS 1024
#define CVW1_BLOCKS 512
#define CVW2_BLOCKS 1024
#define PREP_BLOCKS (GH_BLOCKS + CVX_BLOCKS + CVW1_BLOCKS + CVW2_BLOCKS)

__device__ __forceinline__ void convert_flat(const float* __restrict__ src,
                                             __half* __restrict__ dst,
                                             int n4, int start, int stride) {
#pragma unroll 2
    for (int u = start; u < n4; u += stride) {
        float4 f = reinterpret_cast<const float4*>(src)[u];
        __half h4[4];
        h4[0] = __float2half(f.x); h4[1] = __float2half(f.y);
        h4[2] = __float2half(f.z); h4[3] = __float2half(f.w);
        reinterpret_cast<uint2*>(dst)[u] = *reinterpret_cast<uint2*>(h4);
    }
}

__global__ void __launch_bounds__(256)
prep_kernel(const float* __restrict__ x,
            const float* __restrict__ delta,
            const float* __restrict__ h,
            const float* __restrict__ wih,
            const float* __restrict__ whh,
            const float* __restrict__ wg,
            const float* __restrict__ bg) {
    const int bid = blockIdx.x, t = threadIdx.x;
    if (bid < GH_BLOCKS) {
        // ---- gamma_h: h' = exp(-relu(delta @ Wg^T + bg)) * h ----
        const int j0 = t * 4;
        float w[4][8], b4[4];
#pragma unroll
        for (int k = 0; k < 4; k++) {
            const float4* w4 = reinterpret_cast<const float4*>(wg + (size_t)(j0 + k) * D_DIM);
            float4 lo = w4[0], hi = w4[1];
            w[k][0] = lo.x; w[k][1] = lo.y; w[k][2] = lo.z; w[k][3] = lo.w;
            w[k][4] = hi.x; w[k][5] = hi.y; w[k][6] = hi.z; w[k][7] = hi.w;
            b4[k] = bg[j0 + k];
        }
        const int r0 = bid * GH_ROWS;
#pragma unroll
        for (int b = r0; b < r0 + GH_ROWS; b++) {
            const float4* d4 = reinterpret_cast<const float4*>(delta + (size_t)b * D_DIM);
            float4 a0 = d4[0], a1 = d4[1];
            float4 hv = *reinterpret_cast<const float4*>(h + (size_t)b * H_DIM + j0);
            __half o4[4];
#pragma unroll
            for (int k = 0; k < 4; k++) {
                float s = a0.x * w[k][0] + a0.y * w[k][1] + a0.z * w[k][2] + a0.w * w[k][3]
                        + a1.x * w[k][4] + a1.y * w[k][5] + a1.z * w[k][6] + a1.w * w[k][7]
                        + b4[k];
                float g = __expf(-fmaxf(s, 0.0f));
                o4[k] = __float2half(g * (&hv.x)[k]);
            }
            *reinterpret_cast<uint2*>(g_h16 + (size_t)b * H_DIM + j0) =
                *reinterpret_cast<uint2*>(o4);
        }
    } else if (bid < GH_BLOCKS + CVX_BLOCKS) {
        convert_flat(x, g_x16, BATCH * I_DIM / 4,
                     (bid - GH_BLOCKS) * 256 + t, CVX_BLOCKS * 256);
    } else if (bid < GH_BLOCKS + CVX_BLOCKS + CVW1_BLOCKS) {
        convert_flat(wih, g_wih, G3H * I_DIM / 4,
                     (bid - GH_BLOCKS - CVX_BLOCKS) * 256 + t, CVW1_BLOCKS * 256);
    } else {
        convert_flat(whh, g_whh, G3H * H_DIM / 4,
                     (bid - GH_BLOCKS - CVX_BLOCKS - CVW1_BLOCKS) * 256 + t,
                     CVW2_BLOCKS * 256);
    }
}

// ---------------- producer chunk loader (64 threads, 40 cp16 each) ----------
__device__ __forceinline__ void load_chunk_p(uint32_t stage_sb, int c,
                                             int bm, int jb, int p) {
    const __half* A; const __half* B; int ld_; int kc;
    if (c < NCHUNK1) { A = g_x16; B = g_wih; ld_ = I_DIM; kc = c * KC; }
    else             { A = g_h16; B = g_whh; ld_ = H_DIM; kc = (c - NCHUNK1) * KC; }
#pragma unroll
    for (int i = 0; i < 40; i++) {
        int u = p + i * NPROD;                   // 0..2559
        int row = u >> 3, cc = u & 7;            // 8 x 16B per 128B row
        const __half* src;
        if (row < BM) {
            src = A + (size_t)(bm + row) * ld_ + kc + cc * 8;
        } else {
            int rr = row - BM;                   // 0..191
            int g = rr >> 6, n = rr & 63;
            src = B + (size_t)(jb + n + g * H_DIM) * ld_ + kc + cc * 8;
        }
        cp16(stage_sb + (uint32_t)(row * SPITCH + cc * 16), src);
    }
}

// ---------------- per-chunk MMA: M=32/warp, N=16/warp per gate ---------------
// acc slots: 0 = r_pre (both phases), 1 = z_pre (both), 2 = i_n, 3 = h_n
template <int SN>
__device__ __forceinline__ void mma_chunk(float (&acc)[4][2][2][4],
                                          uint32_t stage_sb,
                                          uint32_t aoff0, uint32_t aoff1,
                                          uint32_t boff) {
#pragma unroll
    for (int ks = 0; ks < 4; ks++) {
        const uint32_t kb = ks * 32;             // k0*2 bytes
        uint32_t a0[4], a1[4];
        LDSM4(a0[0], a0[1], a0[2], a0[3], stage_sb + aoff0 + kb);  // rows wrow..+15
        LDSM4(a1[0], a1[1], a1[2], a1[3], stage_sb + aoff1 + kb);  // rows wrow+16..+31
#pragma unroll
        for (int g = 0; g < 3; g++) {
            const int slot = (g == 0) ? 0 : (g == 1) ? 1 : SN;
            uint32_t b0, b1, b2, b3;
            LDSM4(b0, b1, b2, b3,
                  stage_sb + boff + (uint32_t)(g * 64 * SPITCH) + kb);
            MMA16816(acc[slot][0][0], a0[0], a0[1], a0[2], a0[3], b0, b1);
            MMA16816(acc[slot][0][1], a0[0], a0[1], a0[2], a0[3], b2, b3);
            MMA16816(acc[slot][1][0], a1[0], a1[1], a1[2], a1[3], b0, b1);
            MMA16816(acc[slot][1][1], a1[0], a1[1], a1[2], a1[3], b2, b3);
        }
    }
}

// ---------------- persistent GEMM + GRU epilogue (biases in epilogue) --------
__global__ void __launch_bounds__(NTHREADS, 1)
grud_mma_kernel(float* __restrict__ out,
                const float* __restrict__ bih,
                const float* __restrict__ bhh) {
    extern __shared__ char smem_raw[];
    const uint32_t sb = (smem_u32(smem_raw) + 127) & ~127u;
    const uint32_t bar = sb + NSTAGE * STAGE_BYTES;   // full[s]=bar+16s, empty=+8

    const int tid = threadIdx.x;
    const int wid = tid >> 5, lid = tid & 31;

    if (tid == 0) {
#pragma unroll
        for (int s = 0; s < NSTAGE; s++) {
            MBAR_INIT(bar + s * 16, NPROD);      // full: cp-arrive per producer thread
            MBAR_INIT(bar + s * 16 + 8, 16);     // empty: arrive per consumer warp
        }
    }
    __syncthreads();                             // only CTA-wide barrier

    if (wid >= 16) {
        // ================= producers =================
        const int p = tid - NCONS;               // 0..63
        uint32_t cg = 0;                         // global chunk counter
        for (int t = blockIdx.x; t < NTILES; t += gridDim.x) {
            const int bm = (t & 63) * BM, jb = (t >> 6) * BN;
#pragma unroll 1
            for (int c = 0; c < NCHUNKS; c++, cg++) {
                const int s = cg & 3;
                const uint32_t pw = ((cg >> 2) & 1u) ^ 1u;
                mbar_wait(bar + s * 16 + 8, pw); // stage free?
                load_chunk_p(sb + s * STAGE_BYTES, c, bm, jb, p);
                CP_MBAR_ARRIVE(bar + s * 16);    // full when this chunk's copies land
            }
        }
        return;
    }

    // ================= consumers =================
    const int gid = lid >> 2, tig = lid & 3;
    const int wrow = (wid & 3) * 32;
    const int nq   = (wid >> 2) * 16;
    const int t8 = lid >> 3, ri = lid & 7;
    const uint32_t aoff0 = (uint32_t)((wrow +      (t8 & 1) * 8 + ri) * SPITCH + (t8 >> 1) * 16);
    const uint32_t aoff1 = (uint32_t)((wrow + 16 + (t8 & 1) * 8 + ri) * SPITCH + (t8 >> 1) * 16);
    const uint32_t boff = (uint32_t)((BM + nq + (t8 >> 1) * 8 + ri) * SPITCH + (t8 & 1) * 16);

    uint32_t cg = 0;                             // global chunk counter
    for (int t = blockIdx.x; t < NTILES; t += gridDim.x) {
        const int bm = (t & 63) * BM, jb = (t >> 6) * BN;

        float acc[4][2][2][4];
#pragma unroll
        for (int s = 0; s < 4; s++)
#pragma unroll
            for (int m = 0; m < 2; m++)
#pragma unroll
                for (int n = 0; n < 2; n++)
#pragma unroll
                    for (int e = 0; e < 4; e++) acc[s][m][n][e] = 0.0f;

#pragma unroll 1
        for (int c = 0; c < NCHUNKS; c++, cg++) {
            const int s = cg & 3;
            const uint32_t w = (cg >> 2) & 1u;
            mbar_wait(bar + s * 16, w);          // wait stage full
            const uint32_t stage_sb = sb + s * STAGE_BYTES;
            if (c < NCHUNK1) mma_chunk<2>(acc, stage_sb, aoff0, aoff1, boff);
            else             mma_chunk<3>(acc, stage_sb, aoff0, aoff1, boff);
            if (lid == 0) MBAR_ARRIVE(bar + s * 16 + 8);   // stage consumed
        }

        // ---- epilogue: biases (column-indexed) + GRU math ----
#pragma unroll
        for (int n = 0; n < 2; n++) {
            const int col = jb + nq + n * 8 + tig * 2;
            // per-column bias pairs (fp32, L1/L2 cached)
            float2 rbi = *(const float2*)(bih + col);
            float2 rbh = *(const float2*)(bhh + col);
            float2 zbi = *(const float2*)(bih + H_DIM + col);
            float2 zbh = *(const float2*)(bhh + H_DIM + col);
            float2 inb = *(const float2*)(bih + 2 * H_DIM + col);
            float2 hnb = *(const float2*)(bhh + 2 * H_DIM + col);
            const float rb[2] = { rbi.x + rbh.x, rbi.y + rbh.y };
            const float zb[2] = { zbi.x + zbh.x, zbi.y + zbh.y };
            const float ib[2] = { inb.x, inb.y };
            const float hb[2] = { hnb.x, hnb.y };
#pragma unroll
            for (int m = 0; m < 2; m++) {
                const int r0 = bm + wrow + m * 16 + gid;  // rows r0 and r0+8
                __half2 ha = *(const __half2*)(g_h16 + (size_t)r0 * H_DIM + col);
                __half2 hb2 = *(const __half2*)(g_h16 + (size_t)(r0 + 8) * H_DIM + col);
                float hq[4] = { __half2float(ha.x), __half2float(ha.y),
                                __half2float(hb2.x), __half2float(hb2.y) };
                float o[4];
#pragma unroll
                for (int e = 0; e < 4; e++) {
                    const int ce = e & 1;                  // column parity
                    float r  = 1.0f / (1.0f + __expf(-(acc[0][m][n][e] + rb[ce])));
                    float z  = 1.0f / (1.0f + __expf(-(acc[1][m][n][e] + zb[ce])));
                    float na = acc[2][m][n][e] + ib[ce]
                             + r * (acc[3][m][n][e] + hb[ce]);
                    float nn = 2.0f / (1.0f + __expf(-2.0f * na)) - 1.0f;   // tanh
                    o[e] = nn + z * (hq[e] - nn);
                }
                *(float2*)(out + (size_t)r0 * H_DIM + col)       = make_float2(o[0], o[1]);
                *(float2*)(out + (size_t)(r0 + 8) * H_DIM + col) = make_float2(o[2], o[3]);
            }
        }
    }
}

// ---------------- launch ------------------------------------------------------
extern "C" void kernel_launch(void* const* d_in, const int* in_sizes, int n_in,
                              void* d_out, int out_size) {
    const float* x         = (const float*)d_in[0];
    const float* delta     = (const float*)d_in[1];
    const float* h         = (const float*)d_in[2];
    const float* weight_ih = (const float*)d_in[3];
    const float* weight_hh = (const float*)d_in[4];
    const float* bias_ih   = (const float*)d_in[5];
    const float* bias_hh   = (const float*)d_in[6];
    const float* w_gamma   = (const float*)d_in[7];
    const float* b_gamma   = (const float*)d_in[8];
    float* out = (float*)d_out;

    static int nsm = 0;
    if (nsm == 0) {
        if (cudaDeviceGetAttribute(&nsm, cudaDevAttrMultiProcessorCount, 0)
                != cudaSuccess || nsm <= 0)
            nsm = 148;
    }

    cudaFuncSetAttribute(grud_mma_kernel,
                         cudaFuncAttributeMaxDynamicSharedMemorySize, SMEM_ALLOC);

    prep_kernel<<<PREP_BLOCKS, 256>>>(x, delta, h, weight_ih, weight_hh,
                                      w_gamma, b_gamma);

    grud_mma_kernel<<<nsm, NTHREADS, SMEM_ALLOC>>>(out, bias_ih, bias_hh);
}

// round 15
// speedup vs baseline: 1.5349x; 1.5349x over previous
#include <cuda_runtime.h>
#include <cuda_fp16.h>
#include <cstdint>

// ---------------- problem constants ------------------------------------------
#define BATCH 8192
#define I_DIM 512
#define H_DIM 1024
#define D_DIM 8
#define G3H   3072
// pitched leading dims for fp16 scratch (non-power-of-two BYTE strides:
// 1152 B / 2176 B -> spreads rows across L2 slices; pad region never touched)
#define LDX 576
#define LDH 1088

// ---------------- GEMM tiling (24 real K chunks; biases in epilogue) ---------
#define BM 128               // batch rows per tile
#define BN 64                // hidden cols per tile (per gate; 3 gates)
#define KC 64                // halves per K-chunk
#define NCHUNK1 8            // 512/64   (x @ W_ih^T)
#define NCHUNKS 24           // + 1024/64 (h' @ W_hh^T)
#define NTILES 1024          // (8192/128) * (1024/64)
#define NSTAGE 4
#define SPITCH 144           // bytes per SMEM row (64 halves + 8 pad)
#define SROWS (BM + 3 * BN)  // 128 A rows + 192 B rows = 320
#define STAGE_BYTES (SROWS * SPITCH)            // 46080
#define BAR_BYTES 64
#define SMEM_ALLOC (NSTAGE * STAGE_BYTES + BAR_BYTES + 256)
#define NTHREADS 576         // 16 consumer warps + 2 producer warps
#define NCONS 512
#define NPROD 64

// ---------------- device scratch ---------------------------------------------
__device__ __half g_x16[BATCH * LDX];
__device__ __half g_h16[BATCH * LDH];
__device__ __half g_wih[G3H * LDX];
__device__ __half g_whh[G3H * LDH];

// ---------------- PTX helpers ------------------------------------------------
__device__ __forceinline__ uint32_t smem_u32(const void* p) {
    uint32_t a;
    asm("{ .reg .u64 t; cvta.to.shared.u64 t, %1; cvt.u32.u64 %0, t; }"
        : "=r"(a) : "l"(p));
    return a;
}
__device__ __forceinline__ void cp16(uint32_t dst, const void* src) {
    asm volatile("cp.async.cg.shared.global [%0], [%1], 16;" :: "r"(dst), "l"(src));
}
#define MBAR_INIT(a, c)  asm volatile("mbarrier.init.shared.b64 [%0], %1;" :: "r"(a), "r"(c) : "memory")
#define MBAR_ARRIVE(a)   asm volatile("mbarrier.arrive.shared.b64 _, [%0];" :: "r"(a) : "memory")
#define CP_MBAR_ARRIVE(a) asm volatile("cp.async.mbarrier.arrive.noinc.shared.b64 [%0];" :: "r"(a) : "memory")
__device__ __forceinline__ void mbar_wait(uint32_t mbar, uint32_t parity) {
    asm volatile(
        "{\n\t.reg .pred P;\n"
        "LAB_%=:\n\t"
        "mbarrier.try_wait.parity.acquire.cta.shared::cta.b64 P, [%0], %1, 0x989680;\n\t"
        "@!P bra LAB_%=;\n\t}"
        :: "r"(mbar), "r"(parity) : "memory");
}
#define LDSM4(r0, r1, r2, r3, addr) \
    asm volatile("ldmatrix.sync.aligned.m8n8.x4.shared.b16 {%0,%1,%2,%3}, [%4];" \
        : "=r"(r0), "=r"(r1), "=r"(r2), "=r"(r3) : "r"(addr))
#define MMA16816(acc, a0, a1, a2, a3, b0, b1) \
    asm volatile( \
        "mma.sync.aligned.m16n8k16.row.col.f32.f16.f16.f32 " \
        "{%0,%1,%2,%3}, {%4,%5,%6,%7}, {%8,%9}, {%0,%1,%2,%3};" \
        : "+f"((acc)[0]), "+f"((acc)[1]), "+f"((acc)[2]), "+f"((acc)[3]) \
        : "r"(a0), "r"(a1), "r"(a2), "r"(a3), "r"(b0), "r"(b1))

// ---------------- fused prep kernel ------------------------------------------
// block ranges: [0,2048) gamma_h (4 rows each) | [2048,3072) x | [3072,3584) wih
//               | [3584,4608) whh  — pitched writes, shift-only index math
#define GH_BLOCKS 2048
#define GH_ROWS 4
#define CVX_BLOCKS 1024
#define CVW1_BLOCKS 512
#define CVW2_BLOCKS 1024
#define PREP_BLOCKS (GH_BLOCKS + CVX_BLOCKS + CVW1_BLOCKS + CVW2_BLOCKS)

// QPR = quads per source row (power of two: 128 or 256), LD = dest pitch (halves)
template <int QPR, int LD>
__device__ __forceinline__ void convert_pitched(const float* __restrict__ src,
                                                __half* __restrict__ dst,
                                                int rows, int start, int stride) {
    const int total = rows * QPR;
#pragma unroll 2
    for (int u = start; u < total; u += stride) {
        const int r = u / QPR;                  // compile-time pow2 -> shift
        const int c0 = (u - r * QPR) << 2;
        float4 f = *reinterpret_cast<const float4*>(src + (size_t)r * (QPR * 4) + c0);
        __half h4[4];
        h4[0] = __float2half(f.x); h4[1] = __float2half(f.y);
        h4[2] = __float2half(f.z); h4[3] = __float2half(f.w);
        *reinterpret_cast<uint2*>(dst + (size_t)r * LD + c0) =
            *reinterpret_cast<uint2*>(h4);
    }
}

__global__ void __launch_bounds__(256)
prep_kernel(const float* __restrict__ x,
            const float* __restrict__ delta,
            const float* __restrict__ h,
            const float* __restrict__ wih,
            const float* __restrict__ whh,
            const float* __restrict__ wg,
            const float* __restrict__ bg) {
    const int bid = blockIdx.x, t = threadIdx.x;
    if (bid < GH_BLOCKS) {
        // ---- gamma_h: h' = exp(-relu(delta @ Wg^T + bg)) * h ----
        const int j0 = t * 4;
        float w[4][8], b4[4];
#pragma unroll
        for (int k = 0; k < 4; k++) {
            const float4* w4 = reinterpret_cast<const float4*>(wg + (size_t)(j0 + k) * D_DIM);
            float4 lo = w4[0], hi = w4[1];
            w[k][0] = lo.x; w[k][1] = lo.y; w[k][2] = lo.z; w[k][3] = lo.w;
            w[k][4] = hi.x; w[k][5] = hi.y; w[k][6] = hi.z; w[k][7] = hi.w;
            b4[k] = bg[j0 + k];
        }
        const int r0 = bid * GH_ROWS;
#pragma unroll
        for (int b = r0; b < r0 + GH_ROWS; b++) {
            const float4* d4 = reinterpret_cast<const float4*>(delta + (size_t)b * D_DIM);
            float4 a0 = d4[0], a1 = d4[1];
            float4 hv = *reinterpret_cast<const float4*>(h + (size_t)b * H_DIM + j0);
            __half o4[4];
#pragma unroll
            for (int k = 0; k < 4; k++) {
                float s = a0.x * w[k][0] + a0.y * w[k][1] + a0.z * w[k][2] + a0.w * w[k][3]
                        + a1.x * w[k][4] + a1.y * w[k][5] + a1.z * w[k][6] + a1.w * w[k][7]
                        + b4[k];
                float g = __expf(-fmaxf(s, 0.0f));
                o4[k] = __float2half(g * (&hv.x)[k]);
            }
            *reinterpret_cast<uint2*>(g_h16 + (size_t)b * LDH + j0) =
                *reinterpret_cast<uint2*>(o4);
        }
    } else if (bid < GH_BLOCKS + CVX_BLOCKS) {
        convert_pitched<I_DIM / 4, LDX>(x, g_x16, BATCH,
                                        (bid - GH_BLOCKS) * 256 + t, CVX_BLOCKS * 256);
    } else if (bid < GH_BLOCKS + CVX_BLOCKS + CVW1_BLOCKS) {
        convert_pitched<I_DIM / 4, LDX>(wih, g_wih, G3H,
                                        (bid - GH_BLOCKS - CVX_BLOCKS) * 256 + t,
                                        CVW1_BLOCKS * 256);
    } else {
        convert_pitched<H_DIM / 4, LDH>(whh, g_whh, G3H,
                                        (bid - GH_BLOCKS - CVX_BLOCKS - CVW1_BLOCKS) * 256 + t,
                                        CVW2_BLOCKS * 256);
    }
}

// ---------------- producer chunk loader (64 threads, 40 cp16 each) ----------
__device__ __forceinline__ void load_chunk_p(uint32_t stage_sb, int c,
                                             int bm, int jb, int p) {
    const __half* A; const __half* B; int ld_; int kc;
    if (c < NCHUNK1) { A = g_x16; B = g_wih; ld_ = LDX; kc = c * KC; }
    else             { A = g_h16; B = g_whh; ld_ = LDH; kc = (c - NCHUNK1) * KC; }
#pragma unroll
    for (int i = 0; i < 40; i++) {
        int u = p + i * NPROD;                   // 0..2559
        int row = u >> 3, cc = u & 7;            // 8 x 16B per 128B row
        const __half* src;
        if (row < BM) {
            src = A + (size_t)(bm + row) * ld_ + kc + cc * 8;
        } else {
            int rr = row - BM;                   // 0..191
            int g = rr >> 6, n = rr & 63;
            src = B + (size_t)(jb + n + g * H_DIM) * ld_ + kc + cc * 8;
        }
        cp16(stage_sb + (uint32_t)(row * SPITCH + cc * 16), src);
    }
}

// ---------------- per-chunk MMA: M=32/warp, N=16/warp per gate ---------------
// acc slots: 0 = r_pre (both phases), 1 = z_pre (both), 2 = i_n, 3 = h_n
template <int SN>
__device__ __forceinline__ void mma_chunk(float (&acc)[4][2][2][4],
                                          uint32_t stage_sb,
                                          uint32_t aoff0, uint32_t aoff1,
                                          uint32_t boff) {
#pragma unroll
    for (int ks = 0; ks < 4; ks++) {
        const uint32_t kb = ks * 32;             // k0*2 bytes
        uint32_t a0[4], a1[4];
        LDSM4(a0[0], a0[1], a0[2], a0[3], stage_sb + aoff0 + kb);  // rows wrow..+15
        LDSM4(a1[0], a1[1], a1[2], a1[3], stage_sb + aoff1 + kb);  // rows wrow+16..+31
#pragma unroll
        for (int g = 0; g < 3; g++) {
            const int slot = (g == 0) ? 0 : (g == 1) ? 1 : SN;
            uint32_t b0, b1, b2, b3;
            LDSM4(b0, b1, b2, b3,
                  stage_sb + boff + (uint32_t)(g * 64 * SPITCH) + kb);
            MMA16816(acc[slot][0][0], a0[0], a0[1], a0[2], a0[3], b0, b1);
            MMA16816(acc[slot][0][1], a0[0], a0[1], a0[2], a0[3], b2, b3);
            MMA16816(acc[slot][1][0], a1[0], a1[1], a1[2], a1[3], b0, b1);
            MMA16816(acc[slot][1][1], a1[0], a1[1], a1[2], a1[3], b2, b3);
        }
    }
}

// ---------------- persistent GEMM + GRU epilogue (biases in epilogue) --------
__global__ void __launch_bounds__(NTHREADS, 1)
grud_mma_kernel(float* __restrict__ out,
                const float* __restrict__ bih,
                const float* __restrict__ bhh) {
    extern __shared__ char smem_raw[];
    const uint32_t sb = (smem_u32(smem_raw) + 127) & ~127u;
    const uint32_t bar = sb + NSTAGE * STAGE_BYTES;   // full[s]=bar+16s, empty=+8

    const int tid = threadIdx.x;
    const int wid = tid >> 5, lid = tid & 31;

    if (tid == 0) {
#pragma unroll
        for (int s = 0; s < NSTAGE; s++) {
            MBAR_INIT(bar + s * 16, NPROD);      // full: cp-arrive per producer thread
            MBAR_INIT(bar + s * 16 + 8, 16);     // empty: arrive per consumer warp
        }
    }
    __syncthreads();                             // only CTA-wide barrier

    if (wid >= 16) {
        // ================= producers =================
        const int p = tid - NCONS;               // 0..63
        uint32_t cg = 0;                         // global chunk counter
        for (int t = blockIdx.x; t < NTILES; t += gridDim.x) {
            const int bm = (t & 63) * BM, jb = (t >> 6) * BN;
#pragma unroll 1
            for (int c = 0; c < NCHUNKS; c++, cg++) {
                const int s = cg & 3;
                const uint32_t pw = ((cg >> 2) & 1u) ^ 1u;
                mbar_wait(bar + s * 16 + 8, pw); // stage free?
                load_chunk_p(sb + s * STAGE_BYTES, c, bm, jb, p);
                CP_MBAR_ARRIVE(bar + s * 16);    // full when this chunk's copies land
            }
        }
        return;
    }

    // ================= consumers =================
    const int gid = lid >> 2, tig = lid & 3;
    const int wrow = (wid & 3) * 32;
    const int nq   = (wid >> 2) * 16;
    const int t8 = lid >> 3, ri = lid & 7;
    const uint32_t aoff0 = (uint32_t)((wrow +      (t8 & 1) * 8 + ri) * SPITCH + (t8 >> 1) * 16);
    const uint32_t aoff1 = (uint32_t)((wrow + 16 + (t8 & 1) * 8 + ri) * SPITCH + (t8 >> 1) * 16);
    const uint32_t boff = (uint32_t)((BM + nq + (t8 >> 1) * 8 + ri) * SPITCH + (t8 & 1) * 16);

    uint32_t cg = 0;                             // global chunk counter
    for (int t = blockIdx.x; t < NTILES; t += gridDim.x) {
        const int bm = (t & 63) * BM, jb = (t >> 6) * BN;

        float acc[4][2][2][4];
#pragma unroll
        for (int s = 0; s < 4; s++)
#pragma unroll
            for (int m = 0; m < 2; m++)
#pragma unroll
                for (int n = 0; n < 2; n++)
#pragma unroll
                    for (int e = 0; e < 4; e++) acc[s][m][n][e] = 0.0f;

#pragma unroll 1
        for (int c = 0; c < NCHUNKS; c++, cg++) {
            const int s = cg & 3;
            const uint32_t w = (cg >> 2) & 1u;
            mbar_wait(bar + s * 16, w);          // wait stage full
            const uint32_t stage_sb = sb + s * STAGE_BYTES;
            if (c < NCHUNK1) mma_chunk<2>(acc, stage_sb, aoff0, aoff1, boff);
            else             mma_chunk<3>(acc, stage_sb, aoff0, aoff1, boff);
            if (lid == 0) MBAR_ARRIVE(bar + s * 16 + 8);   // stage consumed
        }

        // ---- epilogue: biases (column-indexed) + GRU math ----
#pragma unroll
        for (int n = 0; n < 2; n++) {
            const int col = jb + nq + n * 8 + tig * 2;
            float2 rbi = *(const float2*)(bih + col);
            float2 rbh = *(const float2*)(bhh + col);
            float2 zbi = *(const float2*)(bih + H_DIM + col);
            float2 zbh = *(const float2*)(bhh + H_DIM + col);
            float2 inb = *(const float2*)(bih + 2 * H_DIM + col);
            float2 hnb = *(const float2*)(bhh + 2 * H_DIM + col);
            const float rb[2] = { rbi.x + rbh.x, rbi.y + rbh.y };
            const float zb[2] = { zbi.x + zbh.x, zbi.y + zbh.y };
            const float ib[2] = { inb.x, inb.y };
            const float hb[2] = { hnb.x, hnb.y };
#pragma unroll
            for (int m = 0; m < 2; m++) {
                const int r0 = bm + wrow + m * 16 + gid;  // rows r0 and r0+8
                __half2 ha  = *(const __half2*)(g_h16 + (size_t)r0 * LDH + col);
                __half2 hb2 = *(const __half2*)(g_h16 + (size_t)(r0 + 8) * LDH + col);
                float hq[4] = { __half2float(ha.x), __half2float(ha.y),
                                __half2float(hb2.x), __half2float(hb2.y) };
                float o[4];
#pragma unroll
                for (int e = 0; e < 4; e++) {
                    const int ce = e & 1;                  // column parity
                    float r  = 1.0f / (1.0f + __expf(-(acc[0][m][n][e] + rb[ce])));
                    float z  = 1.0f / (1.0f + __expf(-(acc[1][m][n][e] + zb[ce])));
                    float na = acc[2][m][n][e] + ib[ce]
                             + r * (acc[3][m][n][e] + hb[ce]);
                    float nn = 2.0f / (1.0f + __expf(-2.0f * na)) - 1.0f;   // tanh
                    o[e] = nn + z * (hq[e] - nn);
                }
                *(float2*)(out + (size_t)r0 * H_DIM + col)       = make_float2(o[0], o[1]);
                *(float2*)(out + (size_t)(r0 + 8) * H_DIM + col) = make_float2(o[2], o[3]);
            }
        }
    }
}

// ---------------- launch ------------------------------------------------------
extern "C" void kernel_launch(void* const* d_in, const int* in_sizes, int n_in,
                              void* d_out, int out_size) {
    const float* x         = (const float*)d_in[0];
    const float* delta     = (const float*)d_in[1];
    const float* h         = (const float*)d_in[2];
    const float* weight_ih = (const float*)d_in[3];
    const float* weight_hh = (const float*)d_in[4];
    const float* bias_ih   = (const float*)d_in[5];
    const float* bias_hh   = (const float*)d_in[6];
    const float* w_gamma   = (const float*)d_in[7];
    const float* b_gamma   = (const float*)d_in[8];
    float* out = (float*)d_out;

    static int nsm = 0;
    if (nsm == 0) {
        if (cudaDeviceGetAttribute(&nsm, cudaDevAttrMultiProcessorCount, 0)
                != cudaSuccess || nsm <= 0)
            nsm = 148;
    }

    cudaFuncSetAttribute(grud_mma_kernel,
                         cudaFuncAttributeMaxDynamicSharedMemorySize, SMEM_ALLOC);

    prep_kernel<<<PREP_BLOCKS, 256>>>(x, delta, h, weight_ih, weight_hh,
                                      w_gamma, b_gamma);

    grud_mma_kernel<<<nsm, NTHREADS, SMEM_ALLOC>>>(out, bias_ih, bias_hh);
}

// round 16
// speedup vs baseline: 1.6443x; 1.0712x over previous
#include <cuda_runtime.h>
#include <cuda_fp16.h>
#include <cstdint>

// ---------------- problem constants ------------------------------------------
#define BATCH 8192
#define I_DIM 512
#define H_DIM 1024
#define D_DIM 8
#define G3H   3072
// pitched leading dims for fp16 scratch (non-power-of-two BYTE strides:
// 1152 B / 2176 B -> spreads rows across L2 slices; pad region never touched)
#define LDX 576
#define LDH 1088

// ---------------- GEMM tiling (24 real K chunks; biases in epilogue) ---------
#define BM 128               // batch rows per tile
#define BN 64                // hidden cols per tile (per gate; 3 gates)
#define KC 64                // halves per K-chunk
#define NCHUNK1 8            // 512/64   (x @ W_ih^T)
#define NCHUNKS 24           // + 1024/64 (h' @ W_hh^T)
#define NTILES 1024          // (8192/128) * (1024/64)
#define NSTAGE 4
#define SPITCH 144           // bytes per SMEM row (64 halves + 8 pad)
#define SROWS (BM + 3 * BN)  // 128 A rows + 192 B rows = 320
#define STAGE_BYTES (SROWS * SPITCH)            // 46080
#define BAR_BYTES 64
#define SMEM_ALLOC (NSTAGE * STAGE_BYTES + BAR_BYTES + 256)
#define NTHREADS 640         // 16 consumer warps + 4 producer warps (1/SMSP)
#define NCONS 512
#define NPROD 128

// ---------------- device scratch ---------------------------------------------
__device__ __half g_x16[BATCH * LDX];
__device__ __half g_h16[BATCH * LDH];
__device__ __half g_wih[G3H * LDX];
__device__ __half g_whh[G3H * LDH];

// ---------------- PTX helpers ------------------------------------------------
__device__ __forceinline__ uint32_t smem_u32(const void* p) {
    uint32_t a;
    asm("{ .reg .u64 t; cvta.to.shared.u64 t, %1; cvt.u32.u64 %0, t; }"
        : "=r"(a) : "l"(p));
    return a;
}
__device__ __forceinline__ void cp16(uint32_t dst, const void* src) {
    asm volatile("cp.async.cg.shared.global [%0], [%1], 16;" :: "r"(dst), "l"(src));
}
#define MBAR_INIT(a, c)  asm volatile("mbarrier.init.shared.b64 [%0], %1;" :: "r"(a), "r"(c) : "memory")
#define MBAR_ARRIVE(a)   asm volatile("mbarrier.arrive.shared.b64 _, [%0];" :: "r"(a) : "memory")
#define CP_MBAR_ARRIVE(a) asm volatile("cp.async.mbarrier.arrive.noinc.shared.b64 [%0];" :: "r"(a) : "memory")
__device__ __forceinline__ void mbar_wait(uint32_t mbar, uint32_t parity) {
    asm volatile(
        "{\n\t.reg .pred P;\n"
        "LAB_%=:\n\t"
        "mbarrier.try_wait.parity.acquire.cta.shared::cta.b64 P, [%0], %1, 0x989680;\n\t"
        "@!P bra LAB_%=;\n\t}"
        :: "r"(mbar), "r"(parity) : "memory");
}
#define LDSM4(r0, r1, r2, r3, addr) \
    asm volatile("ldmatrix.sync.aligned.m8n8.x4.shared.b16 {%0,%1,%2,%3}, [%4];" \
        : "=r"(r0), "=r"(r1), "=r"(r2), "=r"(r3) : "r"(addr))
#define MMA16816(acc, a0, a1, a2, a3, b0, b1) \
    asm volatile( \
        "mma.sync.aligned.m16n8k16.row.col.f32.f16.f16.f32 " \
        "{%0,%1,%2,%3}, {%4,%5,%6,%7}, {%8,%9}, {%0,%1,%2,%3};" \
        : "+f"((acc)[0]), "+f"((acc)[1]), "+f"((acc)[2]), "+f"((acc)[3]) \
        : "r"(a0), "r"(a1), "r"(a2), "r"(a3), "r"(b0), "r"(b1))

// ---------------- fused prep kernel ------------------------------------------
// block ranges: [0,2048) gamma_h (4 rows each) | [2048,3072) x | [3072,3584) wih
//               | [3584,4608) whh  — pitched writes, shift-only index math
#define GH_BLOCKS 2048
#define GH_ROWS 4
#define CVX_BLOCKS 1024
#define CVW1_BLOCKS 512
#define CVW2_BLOCKS 1024
#define PREP_BLOCKS (GH_BLOCKS + CVX_BLOCKS + CVW1_BLOCKS + CVW2_BLOCKS)

// QPR = quads per source row (power of two: 128 or 256), LD = dest pitch (halves)
template <int QPR, int LD>
__device__ __forceinline__ void convert_pitched(const float* __restrict__ src,
                                                __half* __restrict__ dst,
                                                int rows, int start, int stride) {
    const int total = rows * QPR;
#pragma unroll 2
    for (int u = start; u < total; u += stride) {
        const int r = u / QPR;                  // compile-time pow2 -> shift
        const int c0 = (u - r * QPR) << 2;
        float4 f = *reinterpret_cast<const float4*>(src + (size_t)r * (QPR * 4) + c0);
        __half h4[4];
        h4[0] = __float2half(f.x); h4[1] = __float2half(f.y);
        h4[2] = __float2half(f.z); h4[3] = __float2half(f.w);
        *reinterpret_cast<uint2*>(dst + (size_t)r * LD + c0) =
            *reinterpret_cast<uint2*>(h4);
    }
}

__global__ void __launch_bounds__(256)
prep_kernel(const float* __restrict__ x,
            const float* __restrict__ delta,
            const float* __restrict__ h,
            const float* __restrict__ wih,
            const float* __restrict__ whh,
            const float* __restrict__ wg,
            const float* __restrict__ bg) {
    const int bid = blockIdx.x, t = threadIdx.x;
    if (bid < GH_BLOCKS) {
        // ---- gamma_h: h' = exp(-relu(delta @ Wg^T + bg)) * h ----
        const int j0 = t * 4;
        float w[4][8], b4[4];
#pragma unroll
        for (int k = 0; k < 4; k++) {
            const float4* w4 = reinterpret_cast<const float4*>(wg + (size_t)(j0 + k) * D_DIM);
            float4 lo = w4[0], hi = w4[1];
            w[k][0] = lo.x; w[k][1] = lo.y; w[k][2] = lo.z; w[k][3] = lo.w;
            w[k][4] = hi.x; w[k][5] = hi.y; w[k][6] = hi.z; w[k][7] = hi.w;
            b4[k] = bg[j0 + k];
        }
        const int r0 = bid * GH_ROWS;
#pragma unroll
        for (int b = r0; b < r0 + GH_ROWS; b++) {
            const float4* d4 = reinterpret_cast<const float4*>(delta + (size_t)b * D_DIM);
            float4 a0 = d4[0], a1 = d4[1];
            float4 hv = *reinterpret_cast<const float4*>(h + (size_t)b * H_DIM + j0);
            __half o4[4];
#pragma unroll
            for (int k = 0; k < 4; k++) {
                float s = a0.x * w[k][0] + a0.y * w[k][1] + a0.z * w[k][2] + a0.w * w[k][3]
                        + a1.x * w[k][4] + a1.y * w[k][5] + a1.z * w[k][6] + a1.w * w[k][7]
                        + b4[k];
                float g = __expf(-fmaxf(s, 0.0f));
                o4[k] = __float2half(g * (&hv.x)[k]);
            }
            *reinterpret_cast<uint2*>(g_h16 + (size_t)b * LDH + j0) =
                *reinterpret_cast<uint2*>(o4);
        }
    } else if (bid < GH_BLOCKS + CVX_BLOCKS) {
        convert_pitched<I_DIM / 4, LDX>(x, g_x16, BATCH,
                                        (bid - GH_BLOCKS) * 256 + t, CVX_BLOCKS * 256);
    } else if (bid < GH_BLOCKS + CVX_BLOCKS + CVW1_BLOCKS) {
        convert_pitched<I_DIM / 4, LDX>(wih, g_wih, G3H,
                                        (bid - GH_BLOCKS - CVX_BLOCKS) * 256 + t,
                                        CVW1_BLOCKS * 256);
    } else {
        convert_pitched<H_DIM / 4, LDH>(whh, g_whh, G3H,
                                        (bid - GH_BLOCKS - CVX_BLOCKS - CVW1_BLOCKS) * 256 + t,
                                        CVW2_BLOCKS * 256);
    }
}

// ---------------- producer chunk loader (128 threads, 20 cp16 each) ----------
__device__ __forceinline__ void load_chunk_p(uint32_t stage_sb, int c,
                                             int bm, int jb, int p) {
    const __half* A; const __half* B; int ld_; int kc;
    if (c < NCHUNK1) { A = g_x16; B = g_wih; ld_ = LDX; kc = c * KC; }
    else             { A = g_h16; B = g_whh; ld_ = LDH; kc = (c - NCHUNK1) * KC; }
#pragma unroll
    for (int i = 0; i < 20; i++) {
        int u = p + i * NPROD;                   // 0..2559
        int row = u >> 3, cc = u & 7;            // 8 x 16B per 128B row
        const __half* src;
        if (row < BM) {
            src = A + (size_t)(bm + row) * ld_ + kc + cc * 8;
        } else {
            int rr = row - BM;                   // 0..191
            int g = rr >> 6, n = rr & 63;
            src = B + (size_t)(jb + n + g * H_DIM) * ld_ + kc + cc * 8;
        }
        cp16(stage_sb + (uint32_t)(row * SPITCH + cc * 16), src);
    }
}

// ---------------- per-chunk MMA: M=32/warp, N=16/warp per gate ---------------
// acc slots: 0 = r_pre (both phases), 1 = z_pre (both), 2 = i_n, 3 = h_n
template <int SN>
__device__ __forceinline__ void mma_chunk(float (&acc)[4][2][2][4],
                                          uint32_t stage_sb,
                                          uint32_t aoff0, uint32_t aoff1,
                                          uint32_t boff) {
#pragma unroll
    for (int ks = 0; ks < 4; ks++) {
        const uint32_t kb = ks * 32;             // k0*2 bytes
        uint32_t a0[4], a1[4];
        LDSM4(a0[0], a0[1], a0[2], a0[3], stage_sb + aoff0 + kb);  // rows wrow..+15
        LDSM4(a1[0], a1[1], a1[2], a1[3], stage_sb + aoff1 + kb);  // rows wrow+16..+31
#pragma unroll
        for (int g = 0; g < 3; g++) {
            const int slot = (g == 0) ? 0 : (g == 1) ? 1 : SN;
            uint32_t b0, b1, b2, b3;
            LDSM4(b0, b1, b2, b3,
                  stage_sb + boff + (uint32_t)(g * 64 * SPITCH) + kb);
            MMA16816(acc[slot][0][0], a0[0], a0[1], a0[2], a0[3], b0, b1);
            MMA16816(acc[slot][0][1], a0[0], a0[1], a0[2], a0[3], b2, b3);
            MMA16816(acc[slot][1][0], a1[0], a1[1], a1[2], a1[3], b0, b1);
            MMA16816(acc[slot][1][1], a1[0], a1[1], a1[2], a1[3], b2, b3);
        }
    }
}

// ---------------- persistent GEMM + GRU epilogue (biases in epilogue) --------
__global__ void __launch_bounds__(NTHREADS, 1)
grud_mma_kernel(float* __restrict__ out,
                const float* __restrict__ bih,
                const float* __restrict__ bhh) {
    extern __shared__ char smem_raw[];
    const uint32_t sb = (smem_u32(smem_raw) + 127) & ~127u;
    const uint32_t bar = sb + NSTAGE * STAGE_BYTES;   // full[s]=bar+16s, empty=+8

    const int tid = threadIdx.x;
    const int wid = tid >> 5, lid = tid & 31;

    if (tid == 0) {
#pragma unroll
        for (int s = 0; s < NSTAGE; s++) {
            MBAR_INIT(bar + s * 16, NPROD);      // full: cp-arrive per producer thread
            MBAR_INIT(bar + s * 16 + 8, 16);     // empty: arrive per consumer warp
        }
    }
    __syncthreads();                             // only CTA-wide barrier

    if (wid >= 16) {
        // ================= producers (one warp per SMSP) =================
        const int p = tid - NCONS;               // 0..127
        uint32_t cg = 0;                         // global chunk counter
        for (int t = blockIdx.x; t < NTILES; t += gridDim.x) {
            const int bm = (t & 63) * BM, jb = (t >> 6) * BN;
#pragma unroll 1
            for (int c = 0; c < NCHUNKS; c++, cg++) {
                const int s = cg & 3;
                const uint32_t pw = ((cg >> 2) & 1u) ^ 1u;
                mbar_wait(bar + s * 16 + 8, pw); // stage free?
                load_chunk_p(sb + s * STAGE_BYTES, c, bm, jb, p);
                CP_MBAR_ARRIVE(bar + s * 16);    // full when this chunk's copies land
            }
        }
        return;
    }

    // ================= consumers =================
    const int gid = lid >> 2, tig = lid & 3;
    const int wrow = (wid & 3) * 32;
    const int nq   = (wid >> 2) * 16;
    const int t8 = lid >> 3, ri = lid & 7;
    const uint32_t aoff0 = (uint32_t)((wrow +      (t8 & 1) * 8 + ri) * SPITCH + (t8 >> 1) * 16);
    const uint32_t aoff1 = (uint32_t)((wrow + 16 + (t8 & 1) * 8 + ri) * SPITCH + (t8 >> 1) * 16);
    const uint32_t boff = (uint32_t)((BM + nq + (t8 >> 1) * 8 + ri) * SPITCH + (t8 & 1) * 16);

    uint32_t cg = 0;                             // global chunk counter
    for (int t = blockIdx.x; t < NTILES; t += gridDim.x) {
        const int bm = (t & 63) * BM, jb = (t >> 6) * BN;

        float acc[4][2][2][4];
#pragma unroll
        for (int s = 0; s < 4; s++)
#pragma unroll
            for (int m = 0; m < 2; m++)
#pragma unroll
                for (int n = 0; n < 2; n++)
#pragma unroll
                    for (int e = 0; e < 4; e++) acc[s][m][n][e] = 0.0f;

#pragma unroll 1
        for (int c = 0; c < NCHUNKS; c++, cg++) {
            const int s = cg & 3;
            const uint32_t w = (cg >> 2) & 1u;
            mbar_wait(bar + s * 16, w);          // wait stage full
            const uint32_t stage_sb = sb + s * STAGE_BYTES;
            if (c < NCHUNK1) mma_chunk<2>(acc, stage_sb, aoff0, aoff1, boff);
            else             mma_chunk<3>(acc, stage_sb, aoff0, aoff1, boff);
            if (lid == 0) MBAR_ARRIVE(bar + s * 16 + 8);   // stage consumed
        }

        // ---- epilogue: biases (column-indexed) + GRU math ----
#pragma unroll
        for (int n = 0; n < 2; n++) {
            const int col = jb + nq + n * 8 + tig * 2;
            float2 rbi = *(const float2*)(bih + col);
            float2 rbh = *(const float2*)(bhh + col);
            float2 zbi = *(const float2*)(bih + H_DIM + col);
            float2 zbh = *(const float2*)(bhh + H_DIM + col);
            float2 inb = *(const float2*)(bih + 2 * H_DIM + col);
            float2 hnb = *(const float2*)(bhh + 2 * H_DIM + col);
            const float rb[2] = { rbi.x + rbh.x, rbi.y + rbh.y };
            const float zb[2] = { zbi.x + zbh.x, zbi.y + zbh.y };
            const float ib[2] = { inb.x, inb.y };
            const float hb[2] = { hnb.x, hnb.y };
#pragma unroll
            for (int m = 0; m < 2; m++) {
                const int r0 = bm + wrow + m * 16 + gid;  // rows r0 and r0+8
                __half2 ha  = *(const __half2*)(g_h16 + (size_t)r0 * LDH + col);
                __half2 hb2 = *(const __half2*)(g_h16 + (size_t)(r0 + 8) * LDH + col);
                float hq[4] = { __half2float(ha.x), __half2float(ha.y),
                                __half2float(hb2.x), __half2float(hb2.y) };
                float o[4];
#pragma unroll
                for (int e = 0; e < 4; e++) {
                    const int ce = e & 1;                  // column parity
                    float r  = 1.0f / (1.0f + __expf(-(acc[0][m][n][e] + rb[ce])));
                    float z  = 1.0f / (1.0f + __expf(-(acc[1][m][n][e] + zb[ce])));
                    float na = acc[2][m][n][e] + ib[ce]
                             + r * (acc[3][m][n][e] + hb[ce]);
                    float nn = 2.0f / (1.0f + __expf(-2.0f * na)) - 1.0f;   // tanh
                    o[e] = nn + z * (hq[e] - nn);
                }
                *(float2*)(out + (size_t)r0 * H_DIM + col)       = make_float2(o[0], o[1]);
                *(float2*)(out + (size_t)(r0 + 8) * H_DIM + col) = make_float2(o[2], o[3]);
            }
        }
    }
}

// ---------------- launch ------------------------------------------------------
extern "C" void kernel_launch(void* const* d_in, const int* in_sizes, int n_in,
                              void* d_out, int out_size) {
    const float* x         = (const float*)d_in[0];
    const float* delta     = (const float*)d_in[1];
    const float* h         = (const float*)d_in[2];
    const float* weight_ih = (const float*)d_in[3];
    const float* weight_hh = (const float*)d_in[4];
    const float* bias_ih   = (const float*)d_in[5];
    const float* bias_hh   = (const float*)d_in[6];
    const float* w_gamma   = (const float*)d_in[7];
    const float* b_gamma   = (const float*)d_in[8];
    float* out = (float*)d_out;

    static int nsm = 0;
    if (nsm == 0) {
        if (cudaDeviceGetAttribute(&nsm, cudaDevAttrMultiProcessorCount, 0)
                != cudaSuccess || nsm <= 0)
            nsm = 148;
    }

    cudaFuncSetAttribute(grud_mma_kernel,
                         cudaFuncAttributeMaxDynamicSharedMemorySize, SMEM_ALLOC);

    prep_kernel<<<PREP_BLOCKS, 256>>>(x, delta, h, weight_ih, weight_hh,
                                      w_gamma, b_gamma);

    grud_mma_kernel<<<nsm, NTHREADS, SMEM_ALLOC>>>(out, bias_ih, bias_hh);
}

// round 17
// speedup vs baseline: 1.6992x; 1.0334x over previous
#include <cuda_runtime.h>
#include <cuda_fp16.h>
#include <cstdint>

// ---------------- problem constants ------------------------------------------
#define BATCH 8192
#define I_DIM 512
#define H_DIM 1024
#define D_DIM 8
#define G3H   3072

// ---------------- GEMM tiling: chunk-major swizzled scratch + bulk TMA -------
#define BM 128               // batch rows per tile
#define BN 64                // hidden cols per tile (per gate; 3 gates)
#define KC 64                // halves per K-chunk (128 B per row-chunk)
#define NCHUNK1 8            // 512/64   (x @ W_ih^T)
#define NCHUNKS 24           // + 1024/64 (h' @ W_hh^T)
#define NTILES 1024          // (8192/128) * (1024/64)
#define NSTAGE 5
#define A_BYTES (BM * 128)          // 16384, one contiguous slab per chunk
#define BGATE_BYTES (BN * 128)      // 8192 per gate
#define STAGE_BYTES (A_BYTES + 3 * BGATE_BYTES)   // 40960
#define TX_BYTES STAGE_BYTES
#define SMEM_ALLOC (NSTAGE * STAGE_BYTES + 1024 + 128)   // ~206KB, 1 CTA/SM
#define NTHREADS 544         // 16 consumer warps + 1 producer warp
#define NCONS 512

// ---------------- device scratch: chunk-major, SW128-preswizzled -------------
// layout: [plane][row][64 halves]; within each 128B row the 16B units are
// permuted by unit ^= (row & 7)  (the SW128 pattern TMA would apply)
__device__ __align__(1024) __half g_x16c[8  * BATCH * 64];
__device__ __align__(1024) __half g_h16c[16 * BATCH * 64];
__device__ __align__(1024) __half g_wihc[8  * G3H * 64];
__device__ __align__(1024) __half g_whhc[16 * G3H * 64];

// ---------------- PTX helpers ------------------------------------------------
__device__ __forceinline__ uint32_t smem_u32(const void* p) {
    uint32_t a;
    asm("{ .reg .u64 t; cvta.to.shared.u64 t, %1; cvt.u32.u64 %0, t; }"
        : "=r"(a) : "l"(p));
    return a;
}
// bulk async copy gmem -> smem, completion via mbarrier complete_tx
__device__ __forceinline__ void bulk_cp(uint32_t dst, const void* src,
                                        uint32_t bytes, uint32_t mbar) {
    asm volatile(
        "cp.async.bulk.shared::cluster.global.mbarrier::complete_tx::bytes "
        "[%0], [%1], %2, [%3];"
        :: "r"(dst), "l"(src), "r"(bytes), "r"(mbar) : "memory");
}
#define MBAR_INIT(a, c)  asm volatile("mbarrier.init.shared.b64 [%0], %1;" :: "r"(a), "r"(c) : "memory")
#define MBAR_ARRIVE(a)   asm volatile("mbarrier.arrive.shared.b64 _, [%0];" :: "r"(a) : "memory")
#define MBAR_EXPECT_TX(a, n) asm volatile("mbarrier.arrive.expect_tx.shared.b64 _, [%0], %1;" :: "r"(a), "r"(n) : "memory")
__device__ __forceinline__ void mbar_wait(uint32_t mbar, uint32_t parity) {
    asm volatile(
        "{\n\t.reg .pred P;\n"
        "LAB_%=:\n\t"
        "mbarrier.try_wait.parity.acquire.cta.shared::cta.b64 P, [%0], %1, 0x989680;\n\t"
        "@!P bra LAB_%=;\n\t}"
        :: "r"(mbar), "r"(parity) : "memory");
}
#define LDSM4(r0, r1, r2, r3, addr) \
    asm volatile("ldmatrix.sync.aligned.m8n8.x4.shared.b16 {%0,%1,%2,%3}, [%4];" \
        : "=r"(r0), "=r"(r1), "=r"(r2), "=r"(r3) : "r"(addr))
#define MMA16816(acc, a0, a1, a2, a3, b0, b1) \
    asm volatile( \
        "mma.sync.aligned.m16n8k16.row.col.f32.f16.f16.f32 " \
        "{%0,%1,%2,%3}, {%4,%5,%6,%7}, {%8,%9}, {%0,%1,%2,%3};" \
        : "+f"((acc)[0]), "+f"((acc)[1]), "+f"((acc)[2]), "+f"((acc)[3]) \
        : "r"(a0), "r"(a1), "r"(a2), "r"(a3), "r"(b0), "r"(b1))

// ---------------- fused prep kernel ------------------------------------------
// writes chunk-major, SW128-preswizzled scratch
#define GH_BLOCKS 2048
#define GH_ROWS 4
#define CVX_BLOCKS 1024
#define CVW1_BLOCKS 512
#define CVW2_BLOCKS 1024
#define PREP_BLOCKS (GH_BLOCKS + CVX_BLOCKS + CVW1_BLOCKS + CVW2_BLOCKS)

// SC = source row length (halves, power of two); dst chunk-major planes
template <int SC>
__device__ __forceinline__ void convert_cm(const float* __restrict__ src,
                                           __half* __restrict__ dst,
                                           int rows, int start, int stride) {
    constexpr int QPR = SC / 4;                 // quads per source row (pow2)
    const int total = rows * QPR;
#pragma unroll 2
    for (int u = start; u < total; u += stride) {
        const int r = u / QPR;                  // shift (pow2)
        const int c0 = (u - r * QPR) << 2;      // source column (halves)
        float4 f = *reinterpret_cast<const float4*>(src + (size_t)r * SC + c0);
        __half h4[4];
        h4[0] = __float2half(f.x); h4[1] = __float2half(f.y);
        h4[2] = __float2half(f.z); h4[3] = __float2half(f.w);
        const int plane = c0 >> 6;
        char* base = (char*)dst + (((size_t)plane * rows + r) << 7);
        const uint32_t off = (uint32_t)((c0 & 63) * 2) ^ ((uint32_t)(r & 7) << 4);
        *reinterpret_cast<uint2*>(base + off) = *reinterpret_cast<uint2*>(h4);
    }
}

__global__ void __launch_bounds__(256)
prep_kernel(const float* __restrict__ x,
            const float* __restrict__ delta,
            const float* __restrict__ h,
            const float* __restrict__ wih,
            const float* __restrict__ whh,
            const float* __restrict__ wg,
            const float* __restrict__ bg) {
    const int bid = blockIdx.x, t = threadIdx.x;
    if (bid < GH_BLOCKS) {
        // ---- gamma_h: h' = exp(-relu(delta @ Wg^T + bg)) * h ----
        const int j0 = t * 4;
        const int plane = t >> 4;               // j0/64
        const uint32_t cin2 = (uint32_t)((j0 & 63) * 2);
        float w[4][8], b4[4];
#pragma unroll
        for (int k = 0; k < 4; k++) {
            const float4* w4 = reinterpret_cast<const float4*>(wg + (size_t)(j0 + k) * D_DIM);
            float4 lo = w4[0], hi = w4[1];
            w[k][0] = lo.x; w[k][1] = lo.y; w[k][2] = lo.z; w[k][3] = lo.w;
            w[k][4] = hi.x; w[k][5] = hi.y; w[k][6] = hi.z; w[k][7] = hi.w;
            b4[k] = bg[j0 + k];
        }
        const int r0 = bid * GH_ROWS;
#pragma unroll
        for (int b = r0; b < r0 + GH_ROWS; b++) {
            const float4* d4 = reinterpret_cast<const float4*>(delta + (size_t)b * D_DIM);
            float4 a0 = d4[0], a1 = d4[1];
            float4 hv = *reinterpret_cast<const float4*>(h + (size_t)b * H_DIM + j0);
            __half o4[4];
#pragma unroll
            for (int k = 0; k < 4; k++) {
                float s = a0.x * w[k][0] + a0.y * w[k][1] + a0.z * w[k][2] + a0.w * w[k][3]
                        + a1.x * w[k][4] + a1.y * w[k][5] + a1.z * w[k][6] + a1.w * w[k][7]
                        + b4[k];
                float g = __expf(-fmaxf(s, 0.0f));
                o4[k] = __float2half(g * (&hv.x)[k]);
            }
            char* base = (char*)g_h16c + (((size_t)plane * BATCH + b) << 7);
            const uint32_t off = cin2 ^ ((uint32_t)(b & 7) << 4);
            *reinterpret_cast<uint2*>(base + off) = *reinterpret_cast<uint2*>(o4);
        }
    } else if (bid < GH_BLOCKS + CVX_BLOCKS) {
        convert_cm<I_DIM>(x, g_x16c, BATCH,
                          (bid - GH_BLOCKS) * 256 + t, CVX_BLOCKS * 256);
    } else if (bid < GH_BLOCKS + CVX_BLOCKS + CVW1_BLOCKS) {
        convert_cm<I_DIM>(wih, g_wihc, G3H,
                          (bid - GH_BLOCKS - CVX_BLOCKS) * 256 + t, CVW1_BLOCKS * 256);
    } else {
        convert_cm<H_DIM>(whh, g_whhc, G3H,
                          (bid - GH_BLOCKS - CVX_BLOCKS - CVW1_BLOCKS) * 256 + t,
                          CVW2_BLOCKS * 256);
    }
}

// ---------------- per-chunk MMA: swizzled LDSM, M=32/warp, N=16/warp ---------
// acc slots: 0 = r_pre (both phases), 1 = z_pre (both), 2 = i_n, 3 = h_n
template <int SN>
__device__ __forceinline__ void mma_chunk(float (&acc)[4][2][2][4],
                                          uint32_t stage_sb,
                                          uint32_t aoff0, uint32_t aoff1,
                                          uint32_t bbase, uint32_t xm) {
#pragma unroll
    for (int ks = 0; ks < 4; ks++) {
        const uint32_t kb = ks * 32;             // k-step byte offset in 128B row
        uint32_t a0[4], a1[4];
        LDSM4(a0[0], a0[1], a0[2], a0[3], stage_sb + ((aoff0 + kb) ^ xm));
        LDSM4(a1[0], a1[1], a1[2], a1[3], stage_sb + ((aoff1 + kb) ^ xm));
#pragma unroll
        for (int g = 0; g < 3; g++) {
            const int slot = (g == 0) ? 0 : (g == 1) ? 1 : SN;
            uint32_t b0, b1, b2, b3;
            LDSM4(b0, b1, b2, b3,
                  stage_sb + A_BYTES + (uint32_t)(g * BGATE_BYTES) + ((bbase + kb) ^ xm));
            MMA16816(acc[slot][0][0], a0[0], a0[1], a0[2], a0[3], b0, b1);
            MMA16816(acc[slot][0][1], a0[0], a0[1], a0[2], a0[3], b2, b3);
            MMA16816(acc[slot][1][0], a1[0], a1[1], a1[2], a1[3], b0, b1);
            MMA16816(acc[slot][1][1], a1[0], a1[1], a1[2], a1[3], b2, b3);
        }
    }
}

// ---------------- persistent GEMM + GRU epilogue -----------------------------
// 17 warps: 0-15 consumers; warp 16 lane 0 is the single TMA producer.
__global__ void __launch_bounds__(NTHREADS, 1)
grud_mma_kernel(float* __restrict__ out,
                const float* __restrict__ bih,
                const float* __restrict__ bhh) {
    extern __shared__ char smem_raw[];
    const uint32_t sb = (smem_u32(smem_raw) + 1023) & ~1023u;   // 1KB aligned
    const uint32_t bar = sb + NSTAGE * STAGE_BYTES;  // full[s]=bar+16s, empty=+8

    const int tid = threadIdx.x;
    const int wid = tid >> 5, lid = tid & 31;

    if (tid == 0) {
#pragma unroll
        for (int s = 0; s < NSTAGE; s++) {
            MBAR_INIT(bar + s * 16, 1);          // full: 1 expect_tx arrival + tx
            MBAR_INIT(bar + s * 16 + 8, 16);     // empty: one arrive per consumer warp
        }
    }
    __syncthreads();                             // only CTA-wide barrier

    if (tid >= NCONS) {
        // ================= single-thread TMA producer =================
        if (tid == NCONS) {
            int s = 0; uint32_t pw = 1;
            for (int t = blockIdx.x; t < NTILES; t += gridDim.x) {
                const int bm = (t & 63) * BM, jb = (t >> 6) * BN;
#pragma unroll 1
                for (int c = 0; c < NCHUNKS; c++) {
                    mbar_wait(bar + s * 16 + 8, pw);       // stage free?
                    const uint32_t stg = sb + s * STAGE_BYTES;
                    const uint32_t fb = bar + s * 16;
                    MBAR_EXPECT_TX(fb, TX_BYTES);
                    const __half* srcA; const __half* srcBp;
                    if (c < NCHUNK1) {
                        srcA  = g_x16c + (((size_t)c * BATCH + bm) << 6);
                        srcBp = g_wihc + ((size_t)c * G3H << 6);
                    } else {
                        const int c2 = c - NCHUNK1;
                        srcA  = g_h16c + (((size_t)c2 * BATCH + bm) << 6);
                        srcBp = g_whhc + ((size_t)c2 * G3H << 6);
                    }
                    bulk_cp(stg, srcA, A_BYTES, fb);
#pragma unroll
                    for (int g = 0; g < 3; g++)
                        bulk_cp(stg + A_BYTES + g * BGATE_BYTES,
                                srcBp + ((size_t)(g * H_DIM + jb) << 6),
                                BGATE_BYTES, fb);
                    if (++s == NSTAGE) { s = 0; pw ^= 1; }
                }
            }
        }
        return;
    }

    // ================= consumers =================
    const int gid = lid >> 2, tig = lid & 3;
    const int wrow = (wid & 3) * 32;
    const int nq   = (wid >> 2) * 16;
    const int t8 = lid >> 3, ri = lid & 7;
    const uint32_t xm = (uint32_t)ri << 4;       // SW128 lane mask (row&7 == ri)
    const uint32_t aoff0 = (uint32_t)((wrow + (t8 & 1) * 8 + ri) * 128 + (t8 >> 1) * 16);
    const uint32_t aoff1 = aoff0 + 16 * 128;
    const uint32_t bbase = (uint32_t)((nq + (t8 >> 1) * 8 + ri) * 128 + (t8 & 1) * 16);

    int s = 0; uint32_t w = 0;
    for (int t = blockIdx.x; t < NTILES; t += gridDim.x) {
        const int bm = (t & 63) * BM, jb = (t >> 6) * BN;

        float acc[4][2][2][4];
#pragma unroll
        for (int q = 0; q < 4; q++)
#pragma unroll
            for (int m = 0; m < 2; m++)
#pragma unroll
                for (int n = 0; n < 2; n++)
#pragma unroll
                    for (int e = 0; e < 4; e++) acc[q][m][n][e] = 0.0f;

#pragma unroll 1
        for (int c = 0; c < NCHUNKS; c++) {
            mbar_wait(bar + s * 16, w);          // wait stage full
            const uint32_t stage_sb = sb + s * STAGE_BYTES;
            if (c < NCHUNK1) mma_chunk<2>(acc, stage_sb, aoff0, aoff1, bbase, xm);
            else             mma_chunk<3>(acc, stage_sb, aoff0, aoff1, bbase, xm);
            if (lid == 0) MBAR_ARRIVE(bar + s * 16 + 8);   // stage consumed
            if (++s == NSTAGE) { s = 0; w ^= 1; }
        }

        // ---- epilogue: biases (column-indexed) + GRU math ----
        const int hplane = jb >> 6;
#pragma unroll
        for (int n = 0; n < 2; n++) {
            const int colin = nq + n * 8 + tig * 2;     // column within tile
            const int col = jb + colin;
            float2 rbi = *(const float2*)(bih + col);
            float2 rbh = *(const float2*)(bhh + col);
            float2 zbi = *(const float2*)(bih + H_DIM + col);
            float2 zbh = *(const float2*)(bhh + H_DIM + col);
            float2 inb = *(const float2*)(bih + 2 * H_DIM + col);
            float2 hnb = *(const float2*)(bhh + 2 * H_DIM + col);
            const float rb[2] = { rbi.x + rbh.x, rbi.y + rbh.y };
            const float zb[2] = { zbi.x + zbh.x, zbi.y + zbh.y };
            const float ib[2] = { inb.x, inb.y };
            const float hb[2] = { hnb.x, hnb.y };
            const uint32_t hoff = ((uint32_t)(colin * 2)) ^ ((uint32_t)gid << 4);
#pragma unroll
            for (int m = 0; m < 2; m++) {
                const int r0 = bm + wrow + m * 16 + gid;  // rows r0 and r0+8
                const char* hb0 = (const char*)g_h16c + (((size_t)hplane * BATCH + r0) << 7);
                const char* hb1 = (const char*)g_h16c + (((size_t)hplane * BATCH + r0 + 8) << 7);
                __half2 ha  = *(const __half2*)(hb0 + hoff);
                __half2 hb2 = *(const __half2*)(hb1 + hoff);
                float hq[4] = { __half2float(ha.x), __half2float(ha.y),
                                __half2float(hb2.x), __half2float(hb2.y) };
                float o[4];
#pragma unroll
                for (int e = 0; e < 4; e++) {
                    const int ce = e & 1;                  // column parity
                    float r  = 1.0f / (1.0f + __expf(-(acc[0][m][n][e] + rb[ce])));
                    float z  = 1.0f / (1.0f + __expf(-(acc[1][m][n][e] + zb[ce])));
                    float na = acc[2][m][n][e] + ib[ce]
                             + r * (acc[3][m][n][e] + hb[ce]);
                    float nn = 2.0f / (1.0f + __expf(-2.0f * na)) - 1.0f;   // tanh
                    o[e] = nn + z * (hq[e] - nn);
                }
                *(float2*)(out + (size_t)r0 * H_DIM + col)       = make_float2(o[0], o[1]);
                *(float2*)(out + (size_t)(r0 + 8) * H_DIM + col) = make_float2(o[2], o[3]);
            }
        }
    }
}

// ---------------- launch ------------------------------------------------------
extern "C" void kernel_launch(void* const* d_in, const int* in_sizes, int n_in,
                              void* d_out, int out_size) {
    const float* x         = (const float*)d_in[0];
    const float* delta     = (const float*)d_in[1];
    const float* h         = (const float*)d_in[2];
    const float* weight_ih = (const float*)d_in[3];
    const float* weight_hh = (const float*)d_in[4];
    const float* bias_ih   = (const float*)d_in[5];
    const float* bias_hh   = (const float*)d_in[6];
    const float* w_gamma   = (const float*)d_in[7];
    const float* b_gamma   = (const float*)d_in[8];
    float* out = (float*)d_out;

    static int nsm = 0;
    if (nsm == 0) {
        if (cudaDeviceGetAttribute(&nsm, cudaDevAttrMultiProcessorCount, 0)
                != cudaSuccess || nsm <= 0)
            nsm = 148;
    }

    cudaFuncSetAttribute(grud_mma_kernel,
                         cudaFuncAttributeMaxDynamicSharedMemorySize, SMEM_ALLOC);

    prep_kernel<<<PREP_BLOCKS, 256>>>(x, delta, h, weight_ih, weight_hh,
                                      w_gamma, b_gamma);

    grud_mma_kernel<<<nsm, NTHREADS, SMEM_ALLOC>>>(out, bias_ih, bias_hh);
}